// round 13
// baseline (speedup 1.0000x reference)
#include <cuda_runtime.h>
#include <cuda_bf16.h>
#include <cstdint>
#include <cstddef>

// ============================================================================
// ContrastiveLoss (SimCLR NT-Xent), BATCH=4096, DIM=512, TEMP=0.1
// Symmetric-GEMM formulation: sim = R R^T is symmetric, so only the 2080
// upper-triangle 128x128 tiles (of 64x64) are computed. Each off-diagonal
// tile contributes exp-row-sums to row-block i AND exp-col-sums to row-block j.
//   prep : L2-normalize -> bf16 reps[8192,512], fp32 pos[4096], zero g_denom
//   main : mma.sync bf16 128x128x512 tile GEMM + fused exp / dual-sided sums
//   final: loss = (sum log(denom) - (2/T) sum pos) / 8192
// ============================================================================

#define TWO_N   8192
#define NROWS   4096
#define DIMK    512

static constexpr float EXP_SCALE = 14.4269504088896340736f; // log2(e)/TEMP

__device__ __nv_bfloat16 g_reps[(size_t)TWO_N * DIMK];  // 8 MB
__device__ float g_pos[NROWS];
__device__ float g_denom[TWO_N];

// ---- SMEM layout ----
static constexpr int OFF_A     = 0;                    // 128 x 512 bf16 swizzled (131072)
static constexpr int OFF_B     = 131072;               // 3 x (128 x 64 bf16) chunks
static constexpr int B_STRIDE  = 16384;
static constexpr int OFF_RS    = 131072 + 3 * 16384;   // rowsum float[4][128] = 2048
static constexpr int OFF_CS    = OFF_RS + 2048;        // colsum float[2][128] = 1024
static constexpr int SMEM_TOTAL = OFF_CS + 1024;       // 183296 B

// ============================================================================
// helpers
// ============================================================================
__device__ __forceinline__ uint32_t smem_u32(const void* p) {
    uint32_t a;
    asm("{ .reg .u64 t; cvta.to.shared.u64 t, %1; cvt.u32.u64 %0, t; }" : "=r"(a) : "l"(p));
    return a;
}
__device__ __forceinline__ void cp16(uint32_t dst, const void* src) {
    asm volatile("cp.async.cg.shared.global [%0], [%1], 16;" :: "r"(dst), "l"(src) : "memory");
}
__device__ __forceinline__ void ldm4(uint32_t* r, uint32_t addr) {
    asm volatile("ldmatrix.sync.aligned.m8n8.x4.shared.b16 {%0,%1,%2,%3}, [%4];"
                 : "=r"(r[0]), "=r"(r[1]), "=r"(r[2]), "=r"(r[3]) : "r"(addr));
}
__device__ __forceinline__ void mma16816(float* d, const uint32_t* a, uint32_t b0, uint32_t b1) {
    asm volatile("mma.sync.aligned.m16n8k16.row.col.f32.bf16.bf16.f32 "
                 "{%0,%1,%2,%3}, {%4,%5,%6,%7}, {%8,%9}, {%0,%1,%2,%3};"
                 : "+f"(d[0]), "+f"(d[1]), "+f"(d[2]), "+f"(d[3])
                 : "r"(a[0]), "r"(a[1]), "r"(a[2]), "r"(a[3]), "r"(b0), "r"(b1));
}
__device__ __forceinline__ float ex2f(float x) {
    float r;
    asm("ex2.approx.ftz.f32 %0, %1;" : "=f"(r) : "f"(x));
    return r;
}

// ============================================================================
// Kernel 1: normalize + positives + zero denom
// ============================================================================
__global__ void __launch_bounds__(128) simclr_prep(const float* __restrict__ ei,
                                                   const float* __restrict__ ej) {
    const int r = blockIdx.x, t = threadIdx.x;
    const float4 vi = ((const float4*)(ei + (size_t)r * DIMK))[t];
    const float4 vj = ((const float4*)(ej + (size_t)r * DIMK))[t];
    float sii = vi.x*vi.x + vi.y*vi.y + vi.z*vi.z + vi.w*vi.w;
    float sjj = vj.x*vj.x + vj.y*vj.y + vj.z*vj.z + vj.w*vj.w;
    float sij = vi.x*vj.x + vi.y*vj.y + vi.z*vj.z + vi.w*vj.w;
    #pragma unroll
    for (int o = 16; o; o >>= 1) {
        sii += __shfl_down_sync(0xffffffffu, sii, o);
        sjj += __shfl_down_sync(0xffffffffu, sjj, o);
        sij += __shfl_down_sync(0xffffffffu, sij, o);
    }
    __shared__ float sm[3][4];
    const int w = t >> 5, l = t & 31;
    if (l == 0) { sm[0][w] = sii; sm[1][w] = sjj; sm[2][w] = sij; }
    __syncthreads();
    sii = sm[0][0] + sm[0][1] + sm[0][2] + sm[0][3];
    sjj = sm[1][0] + sm[1][1] + sm[1][2] + sm[1][3];
    sij = sm[2][0] + sm[2][1] + sm[2][2] + sm[2][3];
    const float inv_i = 1.0f / fmaxf(sqrtf(sii), 1e-12f);
    const float inv_j = 1.0f / fmaxf(sqrtf(sjj), 1e-12f);
    __nv_bfloat162* oi = (__nv_bfloat162*)(g_reps + (size_t)r * DIMK) + t * 2;
    __nv_bfloat162* oj = (__nv_bfloat162*)(g_reps + (size_t)(r + NROWS) * DIMK) + t * 2;
    oi[0] = __floats2bfloat162_rn(vi.x * inv_i, vi.y * inv_i);
    oi[1] = __floats2bfloat162_rn(vi.z * inv_i, vi.w * inv_i);
    oj[0] = __floats2bfloat162_rn(vj.x * inv_j, vj.y * inv_j);
    oj[1] = __floats2bfloat162_rn(vj.z * inv_j, vj.w * inv_j);
    if (t == 0) { g_pos[r] = sij * inv_i * inv_j; g_denom[r] = 0.f; g_denom[r + NROWS] = 0.f; }
}

// ============================================================================
// Kernel 2: symmetric tile GEMM + fused exp dual-sum
//   grid = 2080 CTAs, one upper-triangle tile (i<=j) each. 256 threads.
//   warp grid 2(m) x 4(n), warp tile 64x32.
// ============================================================================
__global__ void __launch_bounds__(256, 1) simclr_main() {
    extern __shared__ char smem[];
    const uint32_t sb = smem_u32(smem);
    float* rowsum = (float*)(smem + OFF_RS);   // [4][128]
    float* colsum = (float*)(smem + OFF_CS);   // [2][128]
    const int tid = threadIdx.x;
    const int wid = tid >> 5, lane = tid & 31;

    // ---- map blockIdx -> upper-triangle tile (i, j), i<=j ----
    int ti = 0, rem = blockIdx.x;
    while (rem >= 64 - ti) { rem -= 64 - ti; ++ti; }
    const int tj = ti + rem;
    const int rowbase = ti * 128;
    const int colbase = tj * 128;
    const bool diag = (ti == tj);

    // ---- B chunk producer: chunk kc = [128 n][64 k] bf16 swizzled, 16 KB ----
    auto issueB = [&](int kc, int buf) {
        const char* srcb = (const char*)(g_reps + (size_t)colbase * DIMK + kc * 64);
        const uint32_t dbase = sb + OFF_B + buf * B_STRIDE;
        #pragma unroll
        for (int u = 0; u < 4; ++u) {
            const int g = tid + u * 256;
            const int n = g & 127, c = g >> 7;
            cp16(dbase + n * 128 + (((c ^ (n & 7))) << 4),
                 srcb + ((size_t)n * DIMK + c * 8) * 2);
        }
        asm volatile("cp.async.commit_group;" ::: "memory");
    };

    issueB(0, 0);
    issueB(1, 1);

    // ---- resident A tile [128 x 512] bf16, XOR swizzle ----
    {
        const float4* src = (const float4*)(g_reps + (size_t)rowbase * DIMK);
        #pragma unroll
        for (int u = 0; u < 32; ++u) {
            const int g = tid + u * 256;
            const int m = g >> 6, c = g & 63;
            const float4 v = src[(size_t)m * 64 + c];
            *(float4*)(smem + OFF_A + m * 1024 + (((c ^ (m & 7))) << 4)) = v;
        }
    }

    // ---- warp tiling ----
    const int warp_m = wid & 1;
    const int warp_n = wid >> 1;
    const int la = lane & 7;
    const int matsel = lane >> 3;
    const int cA_add = matsel >> 1;

    uint32_t aBase[4]; uint32_t aXor[4];
    #pragma unroll
    for (int mt = 0; mt < 4; ++mt) {
        const int r = warp_m * 64 + mt * 16 + ((matsel & 1) << 3) + la;
        aBase[mt] = sb + OFF_A + r * 1024;
        aXor[mt] = (uint32_t)(r & 7);
    }
    uint32_t bOff[4]; uint32_t bXor[4];
    #pragma unroll
    for (int nt = 0; nt < 4; ++nt) {
        const int n = warp_n * 32 + nt * 8 + la;
        bOff[nt] = (uint32_t)(n * 128);
        bXor[nt] = (uint32_t)(n & 7);
    }
    const int q = matsel;

    float acc[4][4][4];
    #pragma unroll
    for (int mt = 0; mt < 4; ++mt)
        #pragma unroll
        for (int nt = 0; nt < 4; ++nt)
            #pragma unroll
            for (int k = 0; k < 4; ++k) acc[mt][nt][k] = 0.f;

    // ---- mainloop: 8 chunks of 64 K, triple-buffered, 1 barrier/iter ----
    #pragma unroll 1
    for (int kc = 0; kc < 8; ++kc) {
        if (kc < 7) { asm volatile("cp.async.wait_group 1;" ::: "memory"); }
        else        { asm volatile("cp.async.wait_group 0;" ::: "memory"); }
        __syncthreads();
        if (kc + 2 < 8) issueB(kc + 2, (kc + 2) % 3);

        const uint32_t bbase = sb + OFF_B + (kc % 3) * B_STRIDE;
        const int ca0 = kc * 8;
        #pragma unroll
        for (int ks2 = 0; ks2 < 2; ++ks2) {
            const int c0 = ks2 * 4;
            uint32_t b[4][4];
            #pragma unroll
            for (int nt = 0; nt < 4; ++nt)
                ldm4(b[nt], bbase + bOff[nt] + ((((uint32_t)(c0 + q)) ^ bXor[nt]) << 4));
            #pragma unroll
            for (int half = 0; half < 2; ++half) {
                const int ca = ca0 + c0 + half * 2 + cA_add;
                uint32_t a[4][4];
                #pragma unroll
                for (int mt = 0; mt < 4; ++mt)
                    ldm4(a[mt], aBase[mt] + ((((uint32_t)ca) ^ aXor[mt]) << 4));
                #pragma unroll
                for (int mt = 0; mt < 4; ++mt)
                    #pragma unroll
                    for (int nt = 0; nt < 4; ++nt)
                        mma16816(acc[mt][nt], a[mt], b[nt][half * 2], b[nt][half * 2 + 1]);
            }
        }
    }

    // ---- epilogue: exp, mask diag, dual-sided sums ----
    const int rA = lane >> 2;           // 0..7
    const int cA2 = (lane & 3) * 2;
    float rowacc[8];
    #pragma unroll
    for (int k = 0; k < 8; ++k) rowacc[k] = 0.f;
    float colp[4][2];
    #pragma unroll
    for (int nt = 0; nt < 4; ++nt) { colp[nt][0] = 0.f; colp[nt][1] = 0.f; }

    #pragma unroll
    for (int mt = 0; mt < 4; ++mt) {
        const int lrow0 = warp_m * 64 + mt * 16 + rA;   // local row within tile
        #pragma unroll
        for (int nt = 0; nt < 4; ++nt) {
            const int lc = warp_n * 32 + nt * 8 + cA2;  // local col within tile
            float* A4 = acc[mt][nt];
            float e0 = ex2f(A4[0] * EXP_SCALE);
            float e1 = ex2f(A4[1] * EXP_SCALE);
            float e2 = ex2f(A4[2] * EXP_SCALE);
            float e3 = ex2f(A4[3] * EXP_SCALE);
            if (diag) {                                  // exact diagonal mask
                if (lc == lrow0)         e0 = 0.f;
                if (lc + 1 == lrow0)     e1 = 0.f;
                if (lc == lrow0 + 8)     e2 = 0.f;
                if (lc + 1 == lrow0 + 8) e3 = 0.f;
            }
            rowacc[mt * 2 + 0] += e0 + e1;
            rowacc[mt * 2 + 1] += e2 + e3;
            colp[nt][0] += e0 + e2;
            colp[nt][1] += e1 + e3;
        }
    }

    // row reduce across lane&3 (cols) -> lanes with lane&3==0
    #pragma unroll
    for (int k = 0; k < 8; ++k) {
        rowacc[k] += __shfl_xor_sync(0xffffffffu, rowacc[k], 1);
        rowacc[k] += __shfl_xor_sync(0xffffffffu, rowacc[k], 2);
    }
    if ((lane & 3) == 0) {
        #pragma unroll
        for (int mt = 0; mt < 4; ++mt)
            #pragma unroll
            for (int hi = 0; hi < 2; ++hi)
                rowsum[warp_n * 128 + warp_m * 64 + mt * 16 + hi * 8 + rA] = rowacc[mt * 2 + hi];
    }
    // col reduce across lane>>2 (rows) -> lanes 0..3
    #pragma unroll
    for (int nt = 0; nt < 4; ++nt) {
        #pragma unroll
        for (int h = 0; h < 2; ++h) {
            colp[nt][h] += __shfl_xor_sync(0xffffffffu, colp[nt][h], 4);
            colp[nt][h] += __shfl_xor_sync(0xffffffffu, colp[nt][h], 8);
            colp[nt][h] += __shfl_xor_sync(0xffffffffu, colp[nt][h], 16);
        }
    }
    if (lane < 4) {
        #pragma unroll
        for (int nt = 0; nt < 4; ++nt) {
            colsum[warp_m * 128 + warp_n * 32 + nt * 8 + (lane & 3) * 2 + 0] = colp[nt][0];
            colsum[warp_m * 128 + warp_n * 32 + nt * 8 + (lane & 3) * 2 + 1] = colp[nt][1];
        }
    }
    __syncthreads();

    if (tid < 128) {
        const float rs = rowsum[tid] + rowsum[128 + tid] + rowsum[256 + tid] + rowsum[384 + tid];
        atomicAdd(&g_denom[rowbase + tid], rs);
        if (!diag) {
            const float cs2 = colsum[tid] + colsum[128 + tid];
            atomicAdd(&g_denom[colbase + tid], cs2);
        }
    }
}

// ============================================================================
// Kernel 3: final reduction
// ============================================================================
__global__ void __launch_bounds__(256) simclr_final(float* __restrict__ out) {
    const int tid = threadIdx.x;
    float a = 0.f, b = 0.f;
    for (int r = tid; r < TWO_N; r += 256)
        a += logf(g_denom[r]);
    for (int i = tid; i < NROWS; i += 256)
        b += g_pos[i];
    #pragma unroll
    for (int o = 16; o; o >>= 1) {
        a += __shfl_down_sync(0xffffffffu, a, o);
        b += __shfl_down_sync(0xffffffffu, b, o);
    }
    __shared__ float sa[8], sb2[8];
    const int w = tid >> 5, l = tid & 31;
    if (l == 0) { sa[w] = a; sb2[w] = b; }
    __syncthreads();
    if (tid == 0) {
        float A = 0.f, B = 0.f;
        #pragma unroll
        for (int k = 0; k < 8; ++k) { A += sa[k]; B += sb2[k]; }
        out[0] = (A - 20.0f * B) * (1.0f / (float)TWO_N);
    }
}

// ============================================================================
// launch
// ============================================================================
extern "C" void kernel_launch(void* const* d_in, const int* in_sizes, int n_in,
                              void* d_out, int out_size) {
    const float* ei = (const float*)d_in[0];
    const float* ej = (const float*)d_in[1];
    float* out = (float*)d_out;

    cudaFuncSetAttribute(simclr_main, cudaFuncAttributeMaxDynamicSharedMemorySize, SMEM_TOTAL);

    simclr_prep<<<NROWS, 128>>>(ei, ej);
    simclr_main<<<2080, 256, SMEM_TOTAL>>>();
    simclr_final<<<1, 256>>>(out);
}

// round 14
// speedup vs baseline: 1.0101x; 1.0101x over previous
#include <cuda_runtime.h>
#include <cuda_bf16.h>
#include <cstdint>
#include <cstddef>

// ============================================================================
// ContrastiveLoss (SimCLR NT-Xent), BATCH=4096, DIM=512, TEMP=0.1
// Symmetric-GEMM formulation: sim = R R^T is symmetric, so only the 2080
// upper-triangle 128x128 tiles (of 64x64) are computed. Each off-diagonal
// tile contributes exp-row-sums to row-block i AND exp-col-sums to row-block j.
//   prep : L2-normalize -> bf16 reps[8192,512], fp32 pos[4096], zero g_denom
//   main : mma.sync bf16 128x128x512 tile GEMM + fused exp / dual-sided sums
//   final: loss = (sum log(denom) - (2/T) sum pos) / 8192
// ============================================================================

#define TWO_N   8192
#define NROWS   4096
#define DIMK    512

static constexpr float EXP_SCALE = 14.4269504088896340736f; // log2(e)/TEMP

__device__ __nv_bfloat16 g_reps[(size_t)TWO_N * DIMK];  // 8 MB
__device__ float g_pos[NROWS];
__device__ float g_denom[TWO_N];

// ---- SMEM layout ----
static constexpr int OFF_A     = 0;                    // 128 x 512 bf16 swizzled (131072)
static constexpr int OFF_B     = 131072;               // 3 x (128 x 64 bf16) chunks
static constexpr int B_STRIDE  = 16384;
static constexpr int OFF_RS    = 131072 + 3 * 16384;   // rowsum float[4][128] = 2048
static constexpr int OFF_CS    = OFF_RS + 2048;        // colsum float[2][128] = 1024
static constexpr int SMEM_TOTAL = OFF_CS + 1024;       // 183296 B

// ============================================================================
// helpers
// ============================================================================
__device__ __forceinline__ uint32_t smem_u32(const void* p) {
    uint32_t a;
    asm("{ .reg .u64 t; cvta.to.shared.u64 t, %1; cvt.u32.u64 %0, t; }" : "=r"(a) : "l"(p));
    return a;
}
__device__ __forceinline__ void cp16(uint32_t dst, const void* src) {
    asm volatile("cp.async.cg.shared.global [%0], [%1], 16;" :: "r"(dst), "l"(src) : "memory");
}
__device__ __forceinline__ void ldm4(uint32_t* r, uint32_t addr) {
    asm volatile("ldmatrix.sync.aligned.m8n8.x4.shared.b16 {%0,%1,%2,%3}, [%4];"
                 : "=r"(r[0]), "=r"(r[1]), "=r"(r[2]), "=r"(r[3]) : "r"(addr));
}
__device__ __forceinline__ void mma16816(float* d, const uint32_t* a, uint32_t b0, uint32_t b1) {
    asm volatile("mma.sync.aligned.m16n8k16.row.col.f32.bf16.bf16.f32 "
                 "{%0,%1,%2,%3}, {%4,%5,%6,%7}, {%8,%9}, {%0,%1,%2,%3};"
                 : "+f"(d[0]), "+f"(d[1]), "+f"(d[2]), "+f"(d[3])
                 : "r"(a[0]), "r"(a[1]), "r"(a[2]), "r"(a[3]), "r"(b0), "r"(b1));
}
__device__ __forceinline__ float ex2f(float x) {
    float r;
    asm("ex2.approx.ftz.f32 %0, %1;" : "=f"(r) : "f"(x));
    return r;
}

// ============================================================================
// Kernel 1: normalize + positives + zero denom
// ============================================================================
__global__ void __launch_bounds__(128) simclr_prep(const float* __restrict__ ei,
                                                   const float* __restrict__ ej) {
    const int r = blockIdx.x, t = threadIdx.x;
    const float4 vi = ((const float4*)(ei + (size_t)r * DIMK))[t];
    const float4 vj = ((const float4*)(ej + (size_t)r * DIMK))[t];
    float sii = vi.x*vi.x + vi.y*vi.y + vi.z*vi.z + vi.w*vi.w;
    float sjj = vj.x*vj.x + vj.y*vj.y + vj.z*vj.z + vj.w*vj.w;
    float sij = vi.x*vj.x + vi.y*vj.y + vi.z*vj.z + vi.w*vj.w;
    #pragma unroll
    for (int o = 16; o; o >>= 1) {
        sii += __shfl_down_sync(0xffffffffu, sii, o);
        sjj += __shfl_down_sync(0xffffffffu, sjj, o);
        sij += __shfl_down_sync(0xffffffffu, sij, o);
    }
    __shared__ float sm[3][4];
    const int w = t >> 5, l = t & 31;
    if (l == 0) { sm[0][w] = sii; sm[1][w] = sjj; sm[2][w] = sij; }
    __syncthreads();
    sii = sm[0][0] + sm[0][1] + sm[0][2] + sm[0][3];
    sjj = sm[1][0] + sm[1][1] + sm[1][2] + sm[1][3];
    sij = sm[2][0] + sm[2][1] + sm[2][2] + sm[2][3];
    const float inv_i = 1.0f / fmaxf(sqrtf(sii), 1e-12f);
    const float inv_j = 1.0f / fmaxf(sqrtf(sjj), 1e-12f);
    __nv_bfloat162* oi = (__nv_bfloat162*)(g_reps + (size_t)r * DIMK) + t * 2;
    __nv_bfloat162* oj = (__nv_bfloat162*)(g_reps + (size_t)(r + NROWS) * DIMK) + t * 2;
    oi[0] = __floats2bfloat162_rn(vi.x * inv_i, vi.y * inv_i);
    oi[1] = __floats2bfloat162_rn(vi.z * inv_i, vi.w * inv_i);
    oj[0] = __floats2bfloat162_rn(vj.x * inv_j, vj.y * inv_j);
    oj[1] = __floats2bfloat162_rn(vj.z * inv_j, vj.w * inv_j);
    if (t == 0) { g_pos[r] = sij * inv_i * inv_j; g_denom[r] = 0.f; g_denom[r + NROWS] = 0.f; }
}

// ============================================================================
// Kernel 2: symmetric tile GEMM + fused exp dual-sum
//   grid = 2080 CTAs, one upper-triangle tile (i<=j) each. 256 threads.
//   warp grid 2(m) x 4(n), warp tile 64x32.
// ============================================================================
__global__ void __launch_bounds__(256, 1) simclr_main() {
    extern __shared__ char smem[];
    const uint32_t sb = smem_u32(smem);
    float* rowsum = (float*)(smem + OFF_RS);   // [4][128]
    float* colsum = (float*)(smem + OFF_CS);   // [2][128]
    const int tid = threadIdx.x;
    const int wid = tid >> 5, lane = tid & 31;

    // ---- map blockIdx -> upper-triangle tile (i, j), i<=j ----
    int ti = 0, rem = blockIdx.x;
    while (rem >= 64 - ti) { rem -= 64 - ti; ++ti; }
    const int tj = ti + rem;
    const int rowbase = ti * 128;
    const int colbase = tj * 128;
    const bool diag = (ti == tj);

    // ---- B chunk producer: chunk kc = [128 n][64 k] bf16 swizzled, 16 KB ----
    auto issueB = [&](int kc, int buf) {
        const char* srcb = (const char*)(g_reps + (size_t)colbase * DIMK + kc * 64);
        const uint32_t dbase = sb + OFF_B + buf * B_STRIDE;
        #pragma unroll
        for (int u = 0; u < 4; ++u) {
            const int g = tid + u * 256;
            const int n = g & 127, c = g >> 7;
            cp16(dbase + n * 128 + (((c ^ (n & 7))) << 4),
                 srcb + ((size_t)n * DIMK + c * 8) * 2);
        }
        asm volatile("cp.async.commit_group;" ::: "memory");
    };

    issueB(0, 0);
    issueB(1, 1);

    // ---- resident A tile [128 x 512] bf16, XOR swizzle ----
    {
        const float4* src = (const float4*)(g_reps + (size_t)rowbase * DIMK);
        #pragma unroll
        for (int u = 0; u < 32; ++u) {
            const int g = tid + u * 256;
            const int m = g >> 6, c = g & 63;
            const float4 v = src[(size_t)m * 64 + c];
            *(float4*)(smem + OFF_A + m * 1024 + (((c ^ (m & 7))) << 4)) = v;
        }
    }

    // ---- warp tiling ----
    const int warp_m = wid & 1;
    const int warp_n = wid >> 1;
    const int la = lane & 7;
    const int matsel = lane >> 3;
    const int cA_add = matsel >> 1;

    uint32_t aBase[4]; uint32_t aXor[4];
    #pragma unroll
    for (int mt = 0; mt < 4; ++mt) {
        const int r = warp_m * 64 + mt * 16 + ((matsel & 1) << 3) + la;
        aBase[mt] = sb + OFF_A + r * 1024;
        aXor[mt] = (uint32_t)(r & 7);
    }
    uint32_t bOff[4]; uint32_t bXor[4];
    #pragma unroll
    for (int nt = 0; nt < 4; ++nt) {
        const int n = warp_n * 32 + nt * 8 + la;
        bOff[nt] = (uint32_t)(n * 128);
        bXor[nt] = (uint32_t)(n & 7);
    }
    const int q = matsel;

    float acc[4][4][4];
    #pragma unroll
    for (int mt = 0; mt < 4; ++mt)
        #pragma unroll
        for (int nt = 0; nt < 4; ++nt)
            #pragma unroll
            for (int k = 0; k < 4; ++k) acc[mt][nt][k] = 0.f;

    // ---- mainloop: 8 chunks of 64 K, triple-buffered, 1 barrier/iter ----
    #pragma unroll 1
    for (int kc = 0; kc < 8; ++kc) {
        if (kc < 7) { asm volatile("cp.async.wait_group 1;" ::: "memory"); }
        else        { asm volatile("cp.async.wait_group 0;" ::: "memory"); }
        __syncthreads();
        if (kc + 2 < 8) issueB(kc + 2, (kc + 2) % 3);

        const uint32_t bbase = sb + OFF_B + (kc % 3) * B_STRIDE;
        const int ca0 = kc * 8;
        #pragma unroll
        for (int ks2 = 0; ks2 < 2; ++ks2) {
            const int c0 = ks2 * 4;
            uint32_t b[4][4];
            #pragma unroll
            for (int nt = 0; nt < 4; ++nt)
                ldm4(b[nt], bbase + bOff[nt] + ((((uint32_t)(c0 + q)) ^ bXor[nt]) << 4));
            #pragma unroll
            for (int half = 0; half < 2; ++half) {
                const int ca = ca0 + c0 + half * 2 + cA_add;
                uint32_t a[4][4];
                #pragma unroll
                for (int mt = 0; mt < 4; ++mt)
                    ldm4(a[mt], aBase[mt] + ((((uint32_t)ca) ^ aXor[mt]) << 4));
                #pragma unroll
                for (int mt = 0; mt < 4; ++mt)
                    #pragma unroll
                    for (int nt = 0; nt < 4; ++nt)
                        mma16816(acc[mt][nt], a[mt], b[nt][half * 2], b[nt][half * 2 + 1]);
            }
        }
    }

    // ---- epilogue: exp, mask diag, dual-sided sums ----
    const int rA = lane >> 2;           // 0..7
    const int cA2 = (lane & 3) * 2;
    float rowacc[8];
    #pragma unroll
    for (int k = 0; k < 8; ++k) rowacc[k] = 0.f;
    float colp[4][2];
    #pragma unroll
    for (int nt = 0; nt < 4; ++nt) { colp[nt][0] = 0.f; colp[nt][1] = 0.f; }

    #pragma unroll
    for (int mt = 0; mt < 4; ++mt) {
        const int lrow0 = warp_m * 64 + mt * 16 + rA;   // local row within tile
        #pragma unroll
        for (int nt = 0; nt < 4; ++nt) {
            const int lc = warp_n * 32 + nt * 8 + cA2;  // local col within tile
            float* A4 = acc[mt][nt];
            float e0 = ex2f(A4[0] * EXP_SCALE);
            float e1 = ex2f(A4[1] * EXP_SCALE);
            float e2 = ex2f(A4[2] * EXP_SCALE);
            float e3 = ex2f(A4[3] * EXP_SCALE);
            if (diag) {                                  // exact diagonal mask
                if (lc == lrow0)         e0 = 0.f;
                if (lc + 1 == lrow0)     e1 = 0.f;
                if (lc == lrow0 + 8)     e2 = 0.f;
                if (lc + 1 == lrow0 + 8) e3 = 0.f;
            }
            rowacc[mt * 2 + 0] += e0 + e1;
            rowacc[mt * 2 + 1] += e2 + e3;
            colp[nt][0] += e0 + e2;
            colp[nt][1] += e1 + e3;
        }
    }

    // row reduce across lane&3 (cols) -> lanes with lane&3==0
    #pragma unroll
    for (int k = 0; k < 8; ++k) {
        rowacc[k] += __shfl_xor_sync(0xffffffffu, rowacc[k], 1);
        rowacc[k] += __shfl_xor_sync(0xffffffffu, rowacc[k], 2);
    }
    if ((lane & 3) == 0) {
        #pragma unroll
        for (int mt = 0; mt < 4; ++mt)
            #pragma unroll
            for (int hi = 0; hi < 2; ++hi)
                rowsum[warp_n * 128 + warp_m * 64 + mt * 16 + hi * 8 + rA] = rowacc[mt * 2 + hi];
    }
    // col reduce across lane>>2 (rows) -> lanes 0..3
    #pragma unroll
    for (int nt = 0; nt < 4; ++nt) {
        #pragma unroll
        for (int h = 0; h < 2; ++h) {
            colp[nt][h] += __shfl_xor_sync(0xffffffffu, colp[nt][h], 4);
            colp[nt][h] += __shfl_xor_sync(0xffffffffu, colp[nt][h], 8);
            colp[nt][h] += __shfl_xor_sync(0xffffffffu, colp[nt][h], 16);
        }
    }
    if (lane < 4) {
        #pragma unroll
        for (int nt = 0; nt < 4; ++nt) {
            colsum[warp_m * 128 + warp_n * 32 + nt * 8 + (lane & 3) * 2 + 0] = colp[nt][0];
            colsum[warp_m * 128 + warp_n * 32 + nt * 8 + (lane & 3) * 2 + 1] = colp[nt][1];
        }
    }
    __syncthreads();

    if (tid < 128) {
        const float rs = rowsum[tid] + rowsum[128 + tid] + rowsum[256 + tid] + rowsum[384 + tid];
        atomicAdd(&g_denom[rowbase + tid], rs);
        if (!diag) {
            const float cs2 = colsum[tid] + colsum[128 + tid];
            atomicAdd(&g_denom[colbase + tid], cs2);
        }
    }
}

// ============================================================================
// Kernel 3: final reduction
// ============================================================================
__global__ void __launch_bounds__(256) simclr_final(float* __restrict__ out) {
    const int tid = threadIdx.x;
    float a = 0.f, b = 0.f;
    for (int r = tid; r < TWO_N; r += 256)
        a += logf(g_denom[r]);
    for (int i = tid; i < NROWS; i += 256)
        b += g_pos[i];
    #pragma unroll
    for (int o = 16; o; o >>= 1) {
        a += __shfl_down_sync(0xffffffffu, a, o);
        b += __shfl_down_sync(0xffffffffu, b, o);
    }
    __shared__ float sa[8], sb2[8];
    const int w = tid >> 5, l = tid & 31;
    if (l == 0) { sa[w] = a; sb2[w] = b; }
    __syncthreads();
    if (tid == 0) {
        float A = 0.f, B = 0.f;
        #pragma unroll
        for (int k = 0; k < 8; ++k) { A += sa[k]; B += sb2[k]; }
        out[0] = (A - 20.0f * B) * (1.0f / (float)TWO_N);
    }
}

// ============================================================================
// launch
// ============================================================================
extern "C" void kernel_launch(void* const* d_in, const int* in_sizes, int n_in,
                              void* d_out, int out_size) {
    const float* ei = (const float*)d_in[0];
    const float* ej = (const float*)d_in[1];
    float* out = (float*)d_out;

    cudaFuncSetAttribute(simclr_main, cudaFuncAttributeMaxDynamicSharedMemorySize, SMEM_TOTAL);

    simclr_prep<<<NROWS, 128>>>(ei, ej);
    simclr_main<<<2080, 256, SMEM_TOTAL>>>();
    simclr_final<<<1, 256>>>(out);
}

// round 15
// speedup vs baseline: 1.0103x; 1.0002x over previous
#include <cuda_runtime.h>
#include <cuda_bf16.h>
#include <cstdint>
#include <cstddef>

// ============================================================================
// ContrastiveLoss (SimCLR NT-Xent), BATCH=4096, DIM=512, TEMP=0.1
// Symmetric-GEMM formulation: sim = R R^T is symmetric, so only the 2080
// upper-triangle 128x128 tiles (of 64x64) are computed. Each off-diagonal
// tile contributes exp-row-sums to row-block i AND exp-col-sums to row-block j.
//   prep : L2-normalize -> bf16 reps[8192,512], fp32 pos[4096], zero g_denom
//   main : mma.sync bf16 128x128x512 tile GEMM + fused exp / dual-sided sums
//   final: loss = (sum log(denom) - (2/T) sum pos) / 8192
// ============================================================================

#define TWO_N   8192
#define NROWS   4096
#define DIMK    512

static constexpr float EXP_SCALE = 14.4269504088896340736f; // log2(e)/TEMP

__device__ __nv_bfloat16 g_reps[(size_t)TWO_N * DIMK];  // 8 MB
__device__ float g_pos[NROWS];
__device__ float g_denom[TWO_N];

// ---- SMEM layout ----
static constexpr int OFF_A     = 0;                    // 128 x 512 bf16 swizzled (131072)
static constexpr int OFF_B     = 131072;               // 3 x (128 x 64 bf16) chunks
static constexpr int B_STRIDE  = 16384;
static constexpr int OFF_RS    = 131072 + 3 * 16384;   // rowsum float[4][128] = 2048
static constexpr int OFF_CS    = OFF_RS + 2048;        // colsum float[2][128] = 1024
static constexpr int SMEM_TOTAL = OFF_CS + 1024;       // 183296 B

// ============================================================================
// helpers
// ============================================================================
__device__ __forceinline__ uint32_t smem_u32(const void* p) {
    uint32_t a;
    asm("{ .reg .u64 t; cvta.to.shared.u64 t, %1; cvt.u32.u64 %0, t; }" : "=r"(a) : "l"(p));
    return a;
}
__device__ __forceinline__ void cp16(uint32_t dst, const void* src) {
    asm volatile("cp.async.cg.shared.global [%0], [%1], 16;" :: "r"(dst), "l"(src) : "memory");
}
__device__ __forceinline__ void ldm4(uint32_t* r, uint32_t addr) {
    asm volatile("ldmatrix.sync.aligned.m8n8.x4.shared.b16 {%0,%1,%2,%3}, [%4];"
                 : "=r"(r[0]), "=r"(r[1]), "=r"(r[2]), "=r"(r[3]) : "r"(addr));
}
__device__ __forceinline__ void mma16816(float* d, const uint32_t* a, uint32_t b0, uint32_t b1) {
    asm volatile("mma.sync.aligned.m16n8k16.row.col.f32.bf16.bf16.f32 "
                 "{%0,%1,%2,%3}, {%4,%5,%6,%7}, {%8,%9}, {%0,%1,%2,%3};"
                 : "+f"(d[0]), "+f"(d[1]), "+f"(d[2]), "+f"(d[3])
                 : "r"(a[0]), "r"(a[1]), "r"(a[2]), "r"(a[3]), "r"(b0), "r"(b1));
}
__device__ __forceinline__ float ex2f(float x) {
    float r;
    asm("ex2.approx.ftz.f32 %0, %1;" : "=f"(r) : "f"(x));
    return r;
}

// ============================================================================
// Kernel 1: normalize + positives + zero denom
// ============================================================================
__global__ void __launch_bounds__(128) simclr_prep(const float* __restrict__ ei,
                                                   const float* __restrict__ ej) {
    const int r = blockIdx.x, t = threadIdx.x;
    const float4 vi = ((const float4*)(ei + (size_t)r * DIMK))[t];
    const float4 vj = ((const float4*)(ej + (size_t)r * DIMK))[t];
    float sii = vi.x*vi.x + vi.y*vi.y + vi.z*vi.z + vi.w*vi.w;
    float sjj = vj.x*vj.x + vj.y*vj.y + vj.z*vj.z + vj.w*vj.w;
    float sij = vi.x*vj.x + vi.y*vj.y + vi.z*vj.z + vi.w*vj.w;
    #pragma unroll
    for (int o = 16; o; o >>= 1) {
        sii += __shfl_down_sync(0xffffffffu, sii, o);
        sjj += __shfl_down_sync(0xffffffffu, sjj, o);
        sij += __shfl_down_sync(0xffffffffu, sij, o);
    }
    __shared__ float sm[3][4];
    const int w = t >> 5, l = t & 31;
    if (l == 0) { sm[0][w] = sii; sm[1][w] = sjj; sm[2][w] = sij; }
    __syncthreads();
    sii = sm[0][0] + sm[0][1] + sm[0][2] + sm[0][3];
    sjj = sm[1][0] + sm[1][1] + sm[1][2] + sm[1][3];
    sij = sm[2][0] + sm[2][1] + sm[2][2] + sm[2][3];
    const float inv_i = 1.0f / fmaxf(sqrtf(sii), 1e-12f);
    const float inv_j = 1.0f / fmaxf(sqrtf(sjj), 1e-12f);
    __nv_bfloat162* oi = (__nv_bfloat162*)(g_reps + (size_t)r * DIMK) + t * 2;
    __nv_bfloat162* oj = (__nv_bfloat162*)(g_reps + (size_t)(r + NROWS) * DIMK) + t * 2;
    oi[0] = __floats2bfloat162_rn(vi.x * inv_i, vi.y * inv_i);
    oi[1] = __floats2bfloat162_rn(vi.z * inv_i, vi.w * inv_i);
    oj[0] = __floats2bfloat162_rn(vj.x * inv_j, vj.y * inv_j);
    oj[1] = __floats2bfloat162_rn(vj.z * inv_j, vj.w * inv_j);
    if (t == 0) { g_pos[r] = sij * inv_i * inv_j; g_denom[r] = 0.f; g_denom[r + NROWS] = 0.f; }
}

// ============================================================================
// Kernel 2: symmetric tile GEMM + fused exp dual-sum
//   grid = 2080 CTAs, one upper-triangle tile (i<=j) each. 256 threads.
//   warp grid 2(m) x 4(n), warp tile 64x32.
// ============================================================================
__global__ void __launch_bounds__(256, 1) simclr_main() {
    extern __shared__ char smem[];
    const uint32_t sb = smem_u32(smem);
    float* rowsum = (float*)(smem + OFF_RS);   // [4][128]
    float* colsum = (float*)(smem + OFF_CS);   // [2][128]
    const int tid = threadIdx.x;
    const int wid = tid >> 5, lane = tid & 31;

    // ---- map blockIdx -> upper-triangle tile (i, j), i<=j ----
    int ti = 0, rem = blockIdx.x;
    while (rem >= 64 - ti) { rem -= 64 - ti; ++ti; }
    const int tj = ti + rem;
    const int rowbase = ti * 128;
    const int colbase = tj * 128;
    const bool diag = (ti == tj);

    // ---- B chunk producer: chunk kc = [128 n][64 k] bf16 swizzled, 16 KB ----
    auto issueB = [&](int kc, int buf) {
        const char* srcb = (const char*)(g_reps + (size_t)colbase * DIMK + kc * 64);
        const uint32_t dbase = sb + OFF_B + buf * B_STRIDE;
        #pragma unroll
        for (int u = 0; u < 4; ++u) {
            const int g = tid + u * 256;
            const int n = g & 127, c = g >> 7;
            cp16(dbase + n * 128 + (((c ^ (n & 7))) << 4),
                 srcb + ((size_t)n * DIMK + c * 8) * 2);
        }
        asm volatile("cp.async.commit_group;" ::: "memory");
    };

    issueB(0, 0);
    issueB(1, 1);

    // ---- resident A tile [128 x 512] bf16, XOR swizzle ----
    {
        const float4* src = (const float4*)(g_reps + (size_t)rowbase * DIMK);
        #pragma unroll
        for (int u = 0; u < 32; ++u) {
            const int g = tid + u * 256;
            const int m = g >> 6, c = g & 63;
            const float4 v = src[(size_t)m * 64 + c];
            *(float4*)(smem + OFF_A + m * 1024 + (((c ^ (m & 7))) << 4)) = v;
        }
    }

    // ---- warp tiling ----
    const int warp_m = wid & 1;
    const int warp_n = wid >> 1;
    const int la = lane & 7;
    const int matsel = lane >> 3;
    const int cA_add = matsel >> 1;

    uint32_t aBase[4]; uint32_t aXor[4];
    #pragma unroll
    for (int mt = 0; mt < 4; ++mt) {
        const int r = warp_m * 64 + mt * 16 + ((matsel & 1) << 3) + la;
        aBase[mt] = sb + OFF_A + r * 1024;
        aXor[mt] = (uint32_t)(r & 7);
    }
    uint32_t bOff[4]; uint32_t bXor[4];
    #pragma unroll
    for (int nt = 0; nt < 4; ++nt) {
        const int n = warp_n * 32 + nt * 8 + la;
        bOff[nt] = (uint32_t)(n * 128);
        bXor[nt] = (uint32_t)(n & 7);
    }
    const int q = matsel;

    float acc[4][4][4];
    #pragma unroll
    for (int mt = 0; mt < 4; ++mt)
        #pragma unroll
        for (int nt = 0; nt < 4; ++nt)
            #pragma unroll
            for (int k = 0; k < 4; ++k) acc[mt][nt][k] = 0.f;

    // ---- mainloop: 8 chunks of 64 K, triple-buffered, 1 barrier/iter ----
    #pragma unroll 1
    for (int kc = 0; kc < 8; ++kc) {
        if (kc < 7) { asm volatile("cp.async.wait_group 1;" ::: "memory"); }
        else        { asm volatile("cp.async.wait_group 0;" ::: "memory"); }
        __syncthreads();
        if (kc + 2 < 8) issueB(kc + 2, (kc + 2) % 3);

        const uint32_t bbase = sb + OFF_B + (kc % 3) * B_STRIDE;
        const int ca0 = kc * 8;
        #pragma unroll
        for (int ks2 = 0; ks2 < 2; ++ks2) {
            const int c0 = ks2 * 4;
            uint32_t b[4][4];
            #pragma unroll
            for (int nt = 0; nt < 4; ++nt)
                ldm4(b[nt], bbase + bOff[nt] + ((((uint32_t)(c0 + q)) ^ bXor[nt]) << 4));
            #pragma unroll
            for (int half = 0; half < 2; ++half) {
                const int ca = ca0 + c0 + half * 2 + cA_add;
                uint32_t a[4][4];
                #pragma unroll
                for (int mt = 0; mt < 4; ++mt)
                    ldm4(a[mt], aBase[mt] + ((((uint32_t)ca) ^ aXor[mt]) << 4));
                #pragma unroll
                for (int mt = 0; mt < 4; ++mt)
                    #pragma unroll
                    for (int nt = 0; nt < 4; ++nt)
                        mma16816(acc[mt][nt], a[mt], b[nt][half * 2], b[nt][half * 2 + 1]);
            }
        }
    }

    // ---- epilogue: exp, mask diag, dual-sided sums ----
    const int rA = lane >> 2;           // 0..7
    const int cA2 = (lane & 3) * 2;
    float rowacc[8];
    #pragma unroll
    for (int k = 0; k < 8; ++k) rowacc[k] = 0.f;
    float colp[4][2];
    #pragma unroll
    for (int nt = 0; nt < 4; ++nt) { colp[nt][0] = 0.f; colp[nt][1] = 0.f; }

    #pragma unroll
    for (int mt = 0; mt < 4; ++mt) {
        const int lrow0 = warp_m * 64 + mt * 16 + rA;   // local row within tile
        #pragma unroll
        for (int nt = 0; nt < 4; ++nt) {
            const int lc = warp_n * 32 + nt * 8 + cA2;  // local col within tile
            float* A4 = acc[mt][nt];
            float e0 = ex2f(A4[0] * EXP_SCALE);
            float e1 = ex2f(A4[1] * EXP_SCALE);
            float e2 = ex2f(A4[2] * EXP_SCALE);
            float e3 = ex2f(A4[3] * EXP_SCALE);
            if (diag) {                                  // exact diagonal mask
                if (lc == lrow0)         e0 = 0.f;
                if (lc + 1 == lrow0)     e1 = 0.f;
                if (lc == lrow0 + 8)     e2 = 0.f;
                if (lc + 1 == lrow0 + 8) e3 = 0.f;
            }
            rowacc[mt * 2 + 0] += e0 + e1;
            rowacc[mt * 2 + 1] += e2 + e3;
            colp[nt][0] += e0 + e2;
            colp[nt][1] += e1 + e3;
        }
    }

    // row reduce across lane&3 (cols) -> lanes with lane&3==0
    #pragma unroll
    for (int k = 0; k < 8; ++k) {
        rowacc[k] += __shfl_xor_sync(0xffffffffu, rowacc[k], 1);
        rowacc[k] += __shfl_xor_sync(0xffffffffu, rowacc[k], 2);
    }
    if ((lane & 3) == 0) {
        #pragma unroll
        for (int mt = 0; mt < 4; ++mt)
            #pragma unroll
            for (int hi = 0; hi < 2; ++hi)
                rowsum[warp_n * 128 + warp_m * 64 + mt * 16 + hi * 8 + rA] = rowacc[mt * 2 + hi];
    }
    // col reduce across lane>>2 (rows) -> lanes 0..3
    #pragma unroll
    for (int nt = 0; nt < 4; ++nt) {
        #pragma unroll
        for (int h = 0; h < 2; ++h) {
            colp[nt][h] += __shfl_xor_sync(0xffffffffu, colp[nt][h], 4);
            colp[nt][h] += __shfl_xor_sync(0xffffffffu, colp[nt][h], 8);
            colp[nt][h] += __shfl_xor_sync(0xffffffffu, colp[nt][h], 16);
        }
    }
    if (lane < 4) {
        #pragma unroll
        for (int nt = 0; nt < 4; ++nt) {
            colsum[warp_m * 128 + warp_n * 32 + nt * 8 + (lane & 3) * 2 + 0] = colp[nt][0];
            colsum[warp_m * 128 + warp_n * 32 + nt * 8 + (lane & 3) * 2 + 1] = colp[nt][1];
        }
    }
    __syncthreads();

    if (tid < 128) {
        const float rs = rowsum[tid] + rowsum[128 + tid] + rowsum[256 + tid] + rowsum[384 + tid];
        atomicAdd(&g_denom[rowbase + tid], rs);
        if (!diag) {
            const float cs2 = colsum[tid] + colsum[128 + tid];
            atomicAdd(&g_denom[colbase + tid], cs2);
        }
    }
}

// ============================================================================
// Kernel 3: final reduction
// ============================================================================
__global__ void __launch_bounds__(256) simclr_final(float* __restrict__ out) {
    const int tid = threadIdx.x;
    float a = 0.f, b = 0.f;
    for (int r = tid; r < TWO_N; r += 256)
        a += logf(g_denom[r]);
    for (int i = tid; i < NROWS; i += 256)
        b += g_pos[i];
    #pragma unroll
    for (int o = 16; o; o >>= 1) {
        a += __shfl_down_sync(0xffffffffu, a, o);
        b += __shfl_down_sync(0xffffffffu, b, o);
    }
    __shared__ float sa[8], sb2[8];
    const int w = tid >> 5, l = tid & 31;
    if (l == 0) { sa[w] = a; sb2[w] = b; }
    __syncthreads();
    if (tid == 0) {
        float A = 0.f, B = 0.f;
        #pragma unroll
        for (int k = 0; k < 8; ++k) { A += sa[k]; B += sb2[k]; }
        out[0] = (A - 20.0f * B) * (1.0f / (float)TWO_N);
    }
}

// ============================================================================
// launch
// ============================================================================
extern "C" void kernel_launch(void* const* d_in, const int* in_sizes, int n_in,
                              void* d_out, int out_size) {
    const float* ei = (const float*)d_in[0];
    const float* ej = (const float*)d_in[1];
    float* out = (float*)d_out;

    cudaFuncSetAttribute(simclr_main, cudaFuncAttributeMaxDynamicSharedMemorySize, SMEM_TOTAL);

    simclr_prep<<<NROWS, 128>>>(ei, ej);
    simclr_main<<<2080, 256, SMEM_TOTAL>>>();
    simclr_final<<<1, 256>>>(out);
}